// round 2
// baseline (speedup 1.0000x reference)
#include <cuda_runtime.h>
#include <math.h>

// ---------------------------------------------------------------------------
// ChatGLM self-attention, fp32 baseline (R1 = R0 resubmit; R0 bench was an
// infra failure, no metrics produced).
//   SQ=2048 B=2 H=4096 NH=32 HD=128 NG=2 ROT=64
// Stages: QKV GEMM+bias -> rotary(q,k) -> causal GQA flash attention -> dense GEMM
// ---------------------------------------------------------------------------

#define SQL   2048
#define BATCH 2
#define HID   4096
#define NHEAD 32
#define HDIM  128
#define NGRP  2
#define ROTD  64
#define MROWS (SQL*BATCH)                 // 4096 rows (s*B + b)
#define NQKV  (NHEAD*HDIM + 2*NGRP*HDIM)  // 4608
#define KOFF  (NHEAD*HDIM)                // 4096
#define VOFF  (NHEAD*HDIM + NGRP*HDIM)    // 4352
#define CTXW  (NHEAD*HDIM)                // 4096

// Scratch (static device globals: no runtime allocation allowed)
__device__ float g_mixed[(size_t)MROWS * NQKV];   // 75.5 MB
__device__ float g_ctx[(size_t)MROWS * CTXW];     // 67 MB

// ---------------------------------------------------------------------------
// SGEMM: C[M,N] = A[M,K] @ B[K,N] (+ bias[N]), row-major, M%128==N%128==K%8==0
// 128x128 tile, TK=8, 256 threads, 8x8 micro-tile (split 4+4 layout).
// ---------------------------------------------------------------------------
__global__ void __launch_bounds__(256) sgemm_kernel(
    const float* __restrict__ A, const float* __restrict__ B,
    const float* __restrict__ bias, float* __restrict__ C,
    int M, int N, int K)
{
    __shared__ float As[8 * 132];   // A transposed, padded stride 132 (conflict-free stores)
    __shared__ float Bs[8 * 128];

    const int bm = blockIdx.y * 128;
    const int bn = blockIdx.x * 128;
    const int tid = threadIdx.x;
    const int tx = tid & 15;        // 16 col groups
    const int ty = tid >> 4;        // 16 row groups

    float acc[8][8];
#pragma unroll
    for (int i = 0; i < 8; i++)
#pragma unroll
        for (int j = 0; j < 8; j++) acc[i][j] = 0.f;

    for (int k0 = 0; k0 < K; k0 += 8) {
#pragma unroll
        for (int it = 0; it < 4; it++) {
            int i = tid + it * 256;          // 0..1023
            int m = i >> 3, kk = i & 7;
            As[kk * 132 + m] = A[(size_t)(bm + m) * K + k0 + kk];
        }
#pragma unroll
        for (int it = 0; it < 4; it++) {
            int i = tid + it * 256;
            int kk = i >> 7, n = i & 127;
            Bs[kk * 128 + n] = B[(size_t)(k0 + kk) * N + bn + n];
        }
        __syncthreads();
#pragma unroll
        for (int kk = 0; kk < 8; kk++) {
            float a[8], bv[8];
            *(float4*)&a[0]  = *(const float4*)&As[kk * 132 + ty * 4];
            *(float4*)&a[4]  = *(const float4*)&As[kk * 132 + 64 + ty * 4];
            *(float4*)&bv[0] = *(const float4*)&Bs[kk * 128 + tx * 4];
            *(float4*)&bv[4] = *(const float4*)&Bs[kk * 128 + 64 + tx * 4];
#pragma unroll
            for (int i = 0; i < 8; i++)
#pragma unroll
                for (int j = 0; j < 8; j++)
                    acc[i][j] += a[i] * bv[j];
        }
        __syncthreads();
    }

    const int c0 = tx * 4;
    const int c1 = 64 + tx * 4;
#pragma unroll
    for (int i = 0; i < 8; i++) {
        int row = bm + ((i < 4) ? (ty * 4 + i) : (64 + ty * 4 + (i - 4)));
        float* cp = &C[(size_t)row * N + bn];
        float4 w0, w1;
        if (bias) {
            w0 = make_float4(acc[i][0] + bias[bn + c0],
                             acc[i][1] + bias[bn + c0 + 1],
                             acc[i][2] + bias[bn + c0 + 2],
                             acc[i][3] + bias[bn + c0 + 3]);
            w1 = make_float4(acc[i][4] + bias[bn + c1],
                             acc[i][5] + bias[bn + c1 + 1],
                             acc[i][6] + bias[bn + c1 + 2],
                             acc[i][7] + bias[bn + c1 + 3]);
        } else {
            w0 = make_float4(acc[i][0], acc[i][1], acc[i][2], acc[i][3]);
            w1 = make_float4(acc[i][4], acc[i][5], acc[i][6], acc[i][7]);
        }
        *(float4*)&cp[c0] = w0;
        *(float4*)&cp[c1] = w1;
    }
}

// ---------------------------------------------------------------------------
// Rotary: in-place on q (32 heads) and k (2 groups), first 64 dims, pairs (2i,2i+1)
// rope: (SQ, 32, 2) = [cos, sin]
// ---------------------------------------------------------------------------
__global__ void rotary_kernel(float* __restrict__ mixed, const float* __restrict__ rope)
{
    int idx = blockIdx.x * blockDim.x + threadIdx.x;
    const int total = MROWS * 34 * 32;   // rows * (NH+NG) * (ROT/2)
    if (idx >= total) return;
    int i   = idx & 31;                  // pair index
    int hh  = (idx >> 5) % 34;
    int row = idx / (34 * 32);
    int s   = row >> 1;                  // row = s*2 + b
    int col = (hh < NHEAD) ? (hh * HDIM + 2 * i)
                           : (KOFF + (hh - NHEAD) * HDIM + 2 * i);
    float* p = &mixed[(size_t)row * NQKV + col];
    float c  = rope[s * 64 + 2 * i];
    float sn = rope[s * 64 + 2 * i + 1];
    float x0 = p[0], x1 = p[1];
    p[0] = x0 * c - x1 * sn;
    p[1] = x1 * c + x0 * sn;
}

// ---------------------------------------------------------------------------
// Causal GQA flash attention, fp32.
// Grid: (SQ/64, B*NH). CTA: 256 threads. BM=BN=64, HD=128.
// Thread (ty,tx) = (tid/16, tid%16): S micro-tile rows ty*4+i, cols tx+16j.
// O micro-tile: rows ty*4+i, cols tx*4+{0..3} and 64+tx*4+{0..3}.
// Row softmax stats reduced across the 16 tx lanes via half-warp shfl.
// ---------------------------------------------------------------------------
#define ATTN_SMEM_FLOATS (64*128 + 64*132 + 64*128 + 64*68)
#define ATTN_SMEM_BYTES  (ATTN_SMEM_FLOATS * 4)

__device__ __forceinline__ float f4c(const float4& v, int nn) {
    return (nn == 0) ? v.x : (nn == 1) ? v.y : (nn == 2) ? v.z : v.w;
}

__global__ void __launch_bounds__(256, 1) attn_kernel(
    const float* __restrict__ mixed, float* __restrict__ ctx)
{
    extern __shared__ float sm[];
    float* sQ = sm;                  // [64][128]
    float* sK = sQ + 64 * 128;       // [64][132]  (528B row stride: 2-phase b-reads)
    float* sV = sK + 64 * 132;       // [64][128]
    float* sP = sV + 64 * 128;       // [64][68]

    const int qb  = blockIdx.x;
    const int h   = blockIdx.y & 31;
    const int b   = blockIdx.y >> 5;
    const int g   = h >> 4;          // kv group = h / (NH/NG)
    const int tid = threadIdx.x;
    const int ty  = tid >> 4;
    const int tx  = tid & 15;

    // Load Q tile (64 x 128)
#pragma unroll
    for (int it = 0; it < 8; it++) {
        int i  = tid + it * 256;                 // 0..2047
        int r  = i >> 5;
        int c4 = (i & 31) << 2;
        int sp = qb * 64 + r;
        *(float4*)&sQ[r * 128 + c4] =
            *(const float4*)&mixed[(size_t)(sp * 2 + b) * NQKV + h * HDIM + c4];
    }

    float mi[4], li[4], o[4][8];
#pragma unroll
    for (int i = 0; i < 4; i++) {
        mi[i] = -1e30f; li[i] = 0.f;
#pragma unroll
        for (int j = 0; j < 8; j++) o[i][j] = 0.f;
    }

    const float scale = 0.08838834764831845f;    // 1/sqrt(128)
    const int ntiles = qb + 1;

    for (int nt = 0; nt < ntiles; nt++) {
        const int n0 = nt * 64;
        __syncthreads();   // prior PV done (and Q loaded on first iter)
#pragma unroll
        for (int it = 0; it < 8; it++) {
            int i  = tid + it * 256;
            int r  = i >> 5;
            int c4 = (i & 31) << 2;
            size_t roff = (size_t)((n0 + r) * 2 + b) * NQKV;
            *(float4*)&sK[r * 132 + c4] = *(const float4*)&mixed[roff + KOFF + g * HDIM + c4];
            *(float4*)&sV[r * 128 + c4] = *(const float4*)&mixed[roff + VOFF + g * HDIM + c4];
        }
        __syncthreads();

        // S = Q K^T   (4x4 per thread, float4 along k)
        float s[4][4];
#pragma unroll
        for (int i = 0; i < 4; i++)
#pragma unroll
            for (int j = 0; j < 4; j++) s[i][j] = 0.f;

#pragma unroll 8
        for (int k4 = 0; k4 < 128; k4 += 4) {
            float4 a0 = *(const float4*)&sQ[(ty * 4 + 0) * 128 + k4];
            float4 a1 = *(const float4*)&sQ[(ty * 4 + 1) * 128 + k4];
            float4 a2 = *(const float4*)&sQ[(ty * 4 + 2) * 128 + k4];
            float4 a3 = *(const float4*)&sQ[(ty * 4 + 3) * 128 + k4];
            float4 b0 = *(const float4*)&sK[(tx)      * 132 + k4];
            float4 b1 = *(const float4*)&sK[(16 + tx) * 132 + k4];
            float4 b2 = *(const float4*)&sK[(32 + tx) * 132 + k4];
            float4 b3 = *(const float4*)&sK[(48 + tx) * 132 + k4];
#define DOT4(si, av, bv) si += av.x*bv.x + av.y*bv.y + av.z*bv.z + av.w*bv.w
            DOT4(s[0][0], a0, b0); DOT4(s[0][1], a0, b1); DOT4(s[0][2], a0, b2); DOT4(s[0][3], a0, b3);
            DOT4(s[1][0], a1, b0); DOT4(s[1][1], a1, b1); DOT4(s[1][2], a1, b2); DOT4(s[1][3], a1, b3);
            DOT4(s[2][0], a2, b0); DOT4(s[2][1], a2, b1); DOT4(s[2][2], a2, b2); DOT4(s[2][3], a2, b3);
            DOT4(s[3][0], a3, b0); DOT4(s[3][1], a3, b1); DOT4(s[3][2], a3, b2); DOT4(s[3][3], a3, b3);
#undef DOT4
        }

        // Online softmax (per-row, cross-tx half-warp reduction)
#pragma unroll
        for (int i = 0; i < 4; i++) {
            int sp = qb * 64 + ty * 4 + i;
            float rm = -1e30f;
#pragma unroll
            for (int j = 0; j < 4; j++) {
                float v = s[i][j] * scale;
                int kp = n0 + j * 16 + tx;
                if (kp > sp) v = -1e30f;      // causal
                s[i][j] = v;
                rm = fmaxf(rm, v);
            }
#pragma unroll
            for (int d = 8; d >= 1; d >>= 1)
                rm = fmaxf(rm, __shfl_xor_sync(0xffffffffu, rm, d, 16));
            float mnew  = fmaxf(mi[i], rm);
            float alpha = __expf(mi[i] - mnew);
            float rs = 0.f;
#pragma unroll
            for (int j = 0; j < 4; j++) {
                float p = __expf(s[i][j] - mnew);
                sP[(ty * 4 + i) * 68 + j * 16 + tx] = p;
                rs += p;
            }
#pragma unroll
            for (int d = 8; d >= 1; d >>= 1)
                rs += __shfl_xor_sync(0xffffffffu, rs, d, 16);
            li[i] = li[i] * alpha + rs;
            mi[i] = mnew;
#pragma unroll
            for (int jo = 0; jo < 8; jo++) o[i][jo] *= alpha;
        }
        __syncthreads();   // sP visible

        // O += P @ V   (4 rows x 8 cols per thread)
#pragma unroll 4
        for (int n4 = 0; n4 < 64; n4 += 4) {
            float4 af0 = *(const float4*)&sP[(ty * 4 + 0) * 68 + n4];
            float4 af1 = *(const float4*)&sP[(ty * 4 + 1) * 68 + n4];
            float4 af2 = *(const float4*)&sP[(ty * 4 + 2) * 68 + n4];
            float4 af3 = *(const float4*)&sP[(ty * 4 + 3) * 68 + n4];
#pragma unroll
            for (int nn = 0; nn < 4; nn++) {
                float4 v0 = *(const float4*)&sV[(n4 + nn) * 128 + tx * 4];
                float4 v1 = *(const float4*)&sV[(n4 + nn) * 128 + 64 + tx * 4];
                float p0 = f4c(af0, nn), p1 = f4c(af1, nn), p2 = f4c(af2, nn), p3 = f4c(af3, nn);
                o[0][0] += p0 * v0.x; o[0][1] += p0 * v0.y; o[0][2] += p0 * v0.z; o[0][3] += p0 * v0.w;
                o[0][4] += p0 * v1.x; o[0][5] += p0 * v1.y; o[0][6] += p0 * v1.z; o[0][7] += p0 * v1.w;
                o[1][0] += p1 * v0.x; o[1][1] += p1 * v0.y; o[1][2] += p1 * v0.z; o[1][3] += p1 * v0.w;
                o[1][4] += p1 * v1.x; o[1][5] += p1 * v1.y; o[1][6] += p1 * v1.z; o[1][7] += p1 * v1.w;
                o[2][0] += p2 * v0.x; o[2][1] += p2 * v0.y; o[2][2] += p2 * v0.z; o[2][3] += p2 * v0.w;
                o[2][4] += p2 * v1.x; o[2][5] += p2 * v1.y; o[2][6] += p2 * v1.z; o[2][7] += p2 * v1.w;
                o[3][0] += p3 * v0.x; o[3][1] += p3 * v0.y; o[3][2] += p3 * v0.z; o[3][3] += p3 * v0.w;
                o[3][4] += p3 * v1.x; o[3][5] += p3 * v1.y; o[3][6] += p3 * v1.z; o[3][7] += p3 * v1.w;
            }
        }
    }

    // Normalize + write ctx (sq, b, h*128 + d)
#pragma unroll
    for (int i = 0; i < 4; i++) {
        float inv = 1.0f / li[i];
        int sp = qb * 64 + ty * 4 + i;
        float* dst = &ctx[(size_t)(sp * 2 + b) * CTXW + h * HDIM];
        float4 w0 = make_float4(o[i][0] * inv, o[i][1] * inv, o[i][2] * inv, o[i][3] * inv);
        float4 w1 = make_float4(o[i][4] * inv, o[i][5] * inv, o[i][6] * inv, o[i][7] * inv);
        *(float4*)&dst[tx * 4]      = w0;
        *(float4*)&dst[64 + tx * 4] = w1;
    }
}

// ---------------------------------------------------------------------------
// Launch
// ---------------------------------------------------------------------------
extern "C" void kernel_launch(void* const* d_in, const int* in_sizes, int n_in,
                              void* d_out, int out_size)
{
    const float* hidden  = (const float*)d_in[0];
    // d_in[1] = attention_mask (causal triu) — hardcoded, unused
    const float* rope    = (const float*)d_in[2];
    const float* W_qkv   = (const float*)d_in[3];
    const float* b_qkv   = (const float*)d_in[4];
    const float* W_dense = (const float*)d_in[5];
    float* out = (float*)d_out;

    float *mixed = nullptr, *ctx = nullptr;
    cudaGetSymbolAddress((void**)&mixed, g_mixed);
    cudaGetSymbolAddress((void**)&ctx, g_ctx);

    cudaFuncSetAttribute(attn_kernel, cudaFuncAttributeMaxDynamicSharedMemorySize,
                         ATTN_SMEM_BYTES);

    // 1) QKV projection + bias: (4096,4096) @ (4096,4608)
    sgemm_kernel<<<dim3(NQKV / 128, MROWS / 128), 256>>>(
        hidden, W_qkv, b_qkv, mixed, MROWS, NQKV, HID);

    // 2) Rotary on q + k
    {
        int total = MROWS * 34 * 32;
        rotary_kernel<<<(total + 255) / 256, 256>>>(mixed, rope);
    }

    // 3) Causal GQA attention -> ctx
    attn_kernel<<<dim3(SQL / 64, BATCH * NHEAD), 256, ATTN_SMEM_BYTES>>>(mixed, ctx);

    // 4) Dense projection: (4096,4096) @ (4096,4096) -> out
    sgemm_kernel<<<dim3(CTXW / 128, MROWS / 128), 256>>>(
        ctx, W_dense, nullptr, out, MROWS, HID, CTXW);
}

// round 3
// speedup vs baseline: 1.2646x; 1.2646x over previous
#include <cuda_runtime.h>
#include <math.h>
#include <stdint.h>

// ---------------------------------------------------------------------------
// ChatGLM self-attention.  R3: both big GEMMs moved to tf32 tensor cores.
//   QKV GEMM  : 3xTF32 split (near-fp32 accuracy; softmax amplifies its error)
//   dense GEMM: 1xTF32 RNA   (error ~4e-4 lands directly on output, safe)
//   attention : fp32 SIMT flash kernel (unchanged; next round's target)
// ---------------------------------------------------------------------------

#define SQL   2048
#define BATCH 2
#define HID   4096
#define NHEAD 32
#define HDIM  128
#define NGRP  2
#define MROWS (SQL*BATCH)                 // 4096
#define NQKV  (NHEAD*HDIM + 2*NGRP*HDIM)  // 4608
#define KOFF  (NHEAD*HDIM)                // 4096
#define VOFF  (NHEAD*HDIM + NGRP*HDIM)    // 4352
#define CTXW  (NHEAD*HDIM)                // 4096

__device__ float g_mixed[(size_t)MROWS * NQKV];
__device__ float g_ctx[(size_t)MROWS * CTXW];

// ---------------------------------------------------------------------------
// tf32 helpers
// ---------------------------------------------------------------------------
__device__ __forceinline__ uint32_t f2tf32(float x) {
    uint32_t r;
    asm("cvt.rna.tf32.f32 %0, %1;" : "=r"(r) : "f"(x));
    return r;
}

__device__ __forceinline__ void mma_tf32(float* d, const uint32_t* a, const uint32_t* b) {
    asm volatile(
        "mma.sync.aligned.m16n8k8.row.col.f32.tf32.tf32.f32 "
        "{%0,%1,%2,%3}, {%4,%5,%6,%7}, {%8,%9}, {%0,%1,%2,%3};\n"
        : "+f"(d[0]), "+f"(d[1]), "+f"(d[2]), "+f"(d[3])
        : "r"(a[0]), "r"(a[1]), "r"(a[2]), "r"(a[3]), "r"(b[0]), "r"(b[1]));
}

// ---------------------------------------------------------------------------
// 1xTF32 GEMM: C[M,N] = A[M,K] @ B[K,N] (+bias). 128x128x32 tile, 8 warps,
// warp tile 64x32 (4 m16 x 4 n8). Smem stride 136 (==8 mod 32): conflict-free
// fragment loads (banks 8c+r) and conflict-free loader stores.
// ---------------------------------------------------------------------------
#define LDA1 136

__global__ void __launch_bounds__(256, 2) gemm_tf32_1x(
    const float* __restrict__ A, const float* __restrict__ B,
    const float* __restrict__ bias, float* __restrict__ C,
    int M, int N, int K)
{
    __shared__ float As[32 * LDA1];
    __shared__ float Bs[32 * LDA1];

    const int tid  = threadIdx.x;
    const int lane = tid & 31;
    const int wid  = tid >> 5;
    const int wm   = wid & 1;          // 2 warp rows -> 64 M-rows each
    const int wn   = wid >> 1;         // 4 warp cols -> 32 N-cols each
    const int bm   = blockIdx.y * 128;
    const int bn   = blockIdx.x * 128;

    float acc[4][4][4];
#pragma unroll
    for (int mt = 0; mt < 4; mt++)
#pragma unroll
        for (int nt = 0; nt < 4; nt++)
#pragma unroll
            for (int e = 0; e < 4; e++) acc[mt][nt][e] = 0.f;

    const int r = lane >> 2, c = lane & 3;

    for (int k0 = 0; k0 < K; k0 += 32) {
        // A tile 128x32: warp w handles k-quad w; lane = m within 32-group
#pragma unroll
        for (int i = 0; i < 4; i++) {
            int m = lane + 32 * i;
            float4 v = *(const float4*)&A[(size_t)(bm + m) * K + k0 + wid * 4];
            As[(wid * 4 + 0) * LDA1 + m] = __uint_as_float(f2tf32(v.x));
            As[(wid * 4 + 1) * LDA1 + m] = __uint_as_float(f2tf32(v.y));
            As[(wid * 4 + 2) * LDA1 + m] = __uint_as_float(f2tf32(v.z));
            As[(wid * 4 + 3) * LDA1 + m] = __uint_as_float(f2tf32(v.w));
        }
        // B tile 32x128: warp w handles k-rows w, w+8, w+16, w+24; float4 n-loads
#pragma unroll
        for (int i = 0; i < 4; i++) {
            int kk = wid + 8 * i;
            float4 v = *(const float4*)&B[(size_t)(k0 + kk) * N + bn + lane * 4];
            Bs[kk * LDA1 + lane * 4 + 0] = __uint_as_float(f2tf32(v.x));
            Bs[kk * LDA1 + lane * 4 + 1] = __uint_as_float(f2tf32(v.y));
            Bs[kk * LDA1 + lane * 4 + 2] = __uint_as_float(f2tf32(v.z));
            Bs[kk * LDA1 + lane * 4 + 3] = __uint_as_float(f2tf32(v.w));
        }
        __syncthreads();

#pragma unroll
        for (int ks = 0; ks < 4; ks++) {
            const int kb = ks * 8;
            uint32_t af[4][4], bf[4][2];
#pragma unroll
            for (int mt = 0; mt < 4; mt++) {
                int m = wm * 64 + mt * 16 + r;
                af[mt][0] = __float_as_uint(As[(kb + c) * LDA1 + m]);
                af[mt][1] = __float_as_uint(As[(kb + c) * LDA1 + m + 8]);
                af[mt][2] = __float_as_uint(As[(kb + c + 4) * LDA1 + m]);
                af[mt][3] = __float_as_uint(As[(kb + c + 4) * LDA1 + m + 8]);
            }
#pragma unroll
            for (int nt = 0; nt < 4; nt++) {
                int n = wn * 32 + nt * 8 + r;
                bf[nt][0] = __float_as_uint(Bs[(kb + c) * LDA1 + n]);
                bf[nt][1] = __float_as_uint(Bs[(kb + c + 4) * LDA1 + n]);
            }
#pragma unroll
            for (int mt = 0; mt < 4; mt++)
#pragma unroll
                for (int nt = 0; nt < 4; nt++)
                    mma_tf32(acc[mt][nt], af[mt], bf[nt]);
        }
        __syncthreads();
    }

    const int c2 = (lane & 3) * 2;
#pragma unroll
    for (int mt = 0; mt < 4; mt++)
#pragma unroll
        for (int nt = 0; nt < 4; nt++) {
            int row = bm + wm * 64 + mt * 16 + r;
            int col = bn + wn * 32 + nt * 8 + c2;
            float b0 = bias ? bias[col] : 0.f;
            float b1 = bias ? bias[col + 1] : 0.f;
            float2 w0 = make_float2(acc[mt][nt][0] + b0, acc[mt][nt][1] + b1);
            float2 w1 = make_float2(acc[mt][nt][2] + b0, acc[mt][nt][3] + b1);
            *(float2*)&C[(size_t)row * N + col]       = w0;
            *(float2*)&C[(size_t)(row + 8) * N + col] = w1;
        }
}

// ---------------------------------------------------------------------------
// 3xTF32 split GEMM (near-fp32): x = hi + lo, acc += ahi*bhi + alo*bhi + ahi*blo.
// Smem holds float2{hi,lo}, stride 140 float2 (280 floats == 24 mod 32:
// conflict-free 64-bit fragment loads and loader stores).
// ---------------------------------------------------------------------------
#define LDA3 140

__global__ void __launch_bounds__(256, 1) gemm_tf32_3x(
    const float* __restrict__ A, const float* __restrict__ B,
    const float* __restrict__ bias, float* __restrict__ C,
    int M, int N, int K)
{
    extern __shared__ float2 sm2[];
    float2* As2 = sm2;                 // [32][140]
    float2* Bs2 = sm2 + 32 * LDA3;     // [32][140]

    const int tid  = threadIdx.x;
    const int lane = tid & 31;
    const int wid  = tid >> 5;
    const int wm   = wid & 1;
    const int wn   = wid >> 1;
    const int bm   = blockIdx.y * 128;
    const int bn   = blockIdx.x * 128;

    float acc[4][4][4];
#pragma unroll
    for (int mt = 0; mt < 4; mt++)
#pragma unroll
        for (int nt = 0; nt < 4; nt++)
#pragma unroll
            for (int e = 0; e < 4; e++) acc[mt][nt][e] = 0.f;

    const int r = lane >> 2, c = lane & 3;

    for (int k0 = 0; k0 < K; k0 += 32) {
        // A tile: warp = k-quad, lane = m
#pragma unroll
        for (int i = 0; i < 4; i++) {
            int m = lane + 32 * i;
            float4 v = *(const float4*)&A[(size_t)(bm + m) * K + k0 + wid * 4];
            float xs[4] = {v.x, v.y, v.z, v.w};
#pragma unroll
            for (int j = 0; j < 4; j++) {
                uint32_t hb = f2tf32(xs[j]);
                float hf = __uint_as_float(hb);
                uint32_t lb = f2tf32(xs[j] - hf);
                As2[(wid * 4 + j) * LDA3 + m] = make_float2(hf, __uint_as_float(lb));
            }
        }
        // B tile: scalar coalesced loads, n = lane (+32j), kk = wid (+8i)
#pragma unroll
        for (int i = 0; i < 4; i++) {
            int kk = wid + 8 * i;
#pragma unroll
            for (int j = 0; j < 4; j++) {
                int n = lane + 32 * j;
                float x = B[(size_t)(k0 + kk) * N + bn + n];
                uint32_t hb = f2tf32(x);
                float hf = __uint_as_float(hb);
                uint32_t lb = f2tf32(x - hf);
                Bs2[kk * LDA3 + n] = make_float2(hf, __uint_as_float(lb));
            }
        }
        __syncthreads();

#pragma unroll
        for (int ks = 0; ks < 4; ks++) {
            const int kb = ks * 8;
            uint32_t ah[4][4], al[4][4], bh[4][2], bl[4][2];
#pragma unroll
            for (int mt = 0; mt < 4; mt++) {
                int m = wm * 64 + mt * 16 + r;
                float2 v0 = As2[(kb + c) * LDA3 + m];
                float2 v1 = As2[(kb + c) * LDA3 + m + 8];
                float2 v2 = As2[(kb + c + 4) * LDA3 + m];
                float2 v3 = As2[(kb + c + 4) * LDA3 + m + 8];
                ah[mt][0] = __float_as_uint(v0.x); al[mt][0] = __float_as_uint(v0.y);
                ah[mt][1] = __float_as_uint(v1.x); al[mt][1] = __float_as_uint(v1.y);
                ah[mt][2] = __float_as_uint(v2.x); al[mt][2] = __float_as_uint(v2.y);
                ah[mt][3] = __float_as_uint(v3.x); al[mt][3] = __float_as_uint(v3.y);
            }
#pragma unroll
            for (int nt = 0; nt < 4; nt++) {
                int n = wn * 32 + nt * 8 + r;
                float2 v0 = Bs2[(kb + c) * LDA3 + n];
                float2 v1 = Bs2[(kb + c + 4) * LDA3 + n];
                bh[nt][0] = __float_as_uint(v0.x); bl[nt][0] = __float_as_uint(v0.y);
                bh[nt][1] = __float_as_uint(v1.x); bl[nt][1] = __float_as_uint(v1.y);
            }
#pragma unroll
            for (int mt = 0; mt < 4; mt++)
#pragma unroll
                for (int nt = 0; nt < 4; nt++) {
                    mma_tf32(acc[mt][nt], al[mt], bh[nt]);   // lo*hi
                    mma_tf32(acc[mt][nt], ah[mt], bl[nt]);   // hi*lo
                    mma_tf32(acc[mt][nt], ah[mt], bh[nt]);   // hi*hi
                }
        }
        __syncthreads();
    }

    const int c2 = (lane & 3) * 2;
#pragma unroll
    for (int mt = 0; mt < 4; mt++)
#pragma unroll
        for (int nt = 0; nt < 4; nt++) {
            int row = bm + wm * 64 + mt * 16 + r;
            int col = bn + wn * 32 + nt * 8 + c2;
            float b0 = bias ? bias[col] : 0.f;
            float b1 = bias ? bias[col + 1] : 0.f;
            float2 w0 = make_float2(acc[mt][nt][0] + b0, acc[mt][nt][1] + b1);
            float2 w1 = make_float2(acc[mt][nt][2] + b0, acc[mt][nt][3] + b1);
            *(float2*)&C[(size_t)row * N + col]       = w0;
            *(float2*)&C[(size_t)(row + 8) * N + col] = w1;
        }
}

#define GEMM3X_SMEM (2 * 32 * LDA3 * (int)sizeof(float2))

// ---------------------------------------------------------------------------
// Rotary (unchanged)
// ---------------------------------------------------------------------------
__global__ void rotary_kernel(float* __restrict__ mixed, const float* __restrict__ rope)
{
    int idx = blockIdx.x * blockDim.x + threadIdx.x;
    const int total = MROWS * 34 * 32;
    if (idx >= total) return;
    int i   = idx & 31;
    int hh  = (idx >> 5) % 34;
    int row = idx / (34 * 32);
    int s   = row >> 1;
    int col = (hh < NHEAD) ? (hh * HDIM + 2 * i)
                           : (KOFF + (hh - NHEAD) * HDIM + 2 * i);
    float* p = &mixed[(size_t)row * NQKV + col];
    float c  = rope[s * 64 + 2 * i];
    float sn = rope[s * 64 + 2 * i + 1];
    float x0 = p[0], x1 = p[1];
    p[0] = x0 * c - x1 * sn;
    p[1] = x1 * c + x0 * sn;
}

// ---------------------------------------------------------------------------
// Causal GQA flash attention, fp32 (unchanged from R2)
// ---------------------------------------------------------------------------
#define ATTN_SMEM_FLOATS (64*128 + 64*132 + 64*128 + 64*68)
#define ATTN_SMEM_BYTES  (ATTN_SMEM_FLOATS * 4)

__device__ __forceinline__ float f4c(const float4& v, int nn) {
    return (nn == 0) ? v.x : (nn == 1) ? v.y : (nn == 2) ? v.z : v.w;
}

__global__ void __launch_bounds__(256, 1) attn_kernel(
    const float* __restrict__ mixed, float* __restrict__ ctx)
{
    extern __shared__ float sm[];
    float* sQ = sm;
    float* sK = sQ + 64 * 128;
    float* sV = sK + 64 * 132;
    float* sP = sV + 64 * 128;

    const int qb  = blockIdx.x;
    const int h   = blockIdx.y & 31;
    const int b   = blockIdx.y >> 5;
    const int g   = h >> 4;
    const int tid = threadIdx.x;
    const int ty  = tid >> 4;
    const int tx  = tid & 15;

#pragma unroll
    for (int it = 0; it < 8; it++) {
        int i  = tid + it * 256;
        int rr = i >> 5;
        int c4 = (i & 31) << 2;
        int sp = qb * 64 + rr;
        *(float4*)&sQ[rr * 128 + c4] =
            *(const float4*)&mixed[(size_t)(sp * 2 + b) * NQKV + h * HDIM + c4];
    }

    float mi[4], li[4], o[4][8];
#pragma unroll
    for (int i = 0; i < 4; i++) {
        mi[i] = -1e30f; li[i] = 0.f;
#pragma unroll
        for (int j = 0; j < 8; j++) o[i][j] = 0.f;
    }

    const float scale = 0.08838834764831845f;
    const int ntiles = qb + 1;

    for (int nt = 0; nt < ntiles; nt++) {
        const int n0 = nt * 64;
        __syncthreads();
#pragma unroll
        for (int it = 0; it < 8; it++) {
            int i  = tid + it * 256;
            int rr = i >> 5;
            int c4 = (i & 31) << 2;
            size_t roff = (size_t)((n0 + rr) * 2 + b) * NQKV;
            *(float4*)&sK[rr * 132 + c4] = *(const float4*)&mixed[roff + KOFF + g * HDIM + c4];
            *(float4*)&sV[rr * 128 + c4] = *(const float4*)&mixed[roff + VOFF + g * HDIM + c4];
        }
        __syncthreads();

        float s[4][4];
#pragma unroll
        for (int i = 0; i < 4; i++)
#pragma unroll
            for (int j = 0; j < 4; j++) s[i][j] = 0.f;

#pragma unroll 8
        for (int k4 = 0; k4 < 128; k4 += 4) {
            float4 a0 = *(const float4*)&sQ[(ty * 4 + 0) * 128 + k4];
            float4 a1 = *(const float4*)&sQ[(ty * 4 + 1) * 128 + k4];
            float4 a2 = *(const float4*)&sQ[(ty * 4 + 2) * 128 + k4];
            float4 a3 = *(const float4*)&sQ[(ty * 4 + 3) * 128 + k4];
            float4 b0 = *(const float4*)&sK[(tx)      * 132 + k4];
            float4 b1 = *(const float4*)&sK[(16 + tx) * 132 + k4];
            float4 b2 = *(const float4*)&sK[(32 + tx) * 132 + k4];
            float4 b3 = *(const float4*)&sK[(48 + tx) * 132 + k4];
#define DOT4(si, av, bv) si += av.x*bv.x + av.y*bv.y + av.z*bv.z + av.w*bv.w
            DOT4(s[0][0], a0, b0); DOT4(s[0][1], a0, b1); DOT4(s[0][2], a0, b2); DOT4(s[0][3], a0, b3);
            DOT4(s[1][0], a1, b0); DOT4(s[1][1], a1, b1); DOT4(s[1][2], a1, b2); DOT4(s[1][3], a1, b3);
            DOT4(s[2][0], a2, b0); DOT4(s[2][1], a2, b1); DOT4(s[2][2], a2, b2); DOT4(s[2][3], a2, b3);
            DOT4(s[3][0], a3, b0); DOT4(s[3][1], a3, b1); DOT4(s[3][2], a3, b2); DOT4(s[3][3], a3, b3);
#undef DOT4
        }

#pragma unroll
        for (int i = 0; i < 4; i++) {
            int sp = qb * 64 + ty * 4 + i;
            float rm = -1e30f;
#pragma unroll
            for (int j = 0; j < 4; j++) {
                float v = s[i][j] * scale;
                int kp = n0 + j * 16 + tx;
                if (kp > sp) v = -1e30f;
                s[i][j] = v;
                rm = fmaxf(rm, v);
            }
#pragma unroll
            for (int d = 8; d >= 1; d >>= 1)
                rm = fmaxf(rm, __shfl_xor_sync(0xffffffffu, rm, d, 16));
            float mnew  = fmaxf(mi[i], rm);
            float alpha = __expf(mi[i] - mnew);
            float rs = 0.f;
#pragma unroll
            for (int j = 0; j < 4; j++) {
                float p = __expf(s[i][j] - mnew);
                sP[(ty * 4 + i) * 68 + j * 16 + tx] = p;
                rs += p;
            }
#pragma unroll
            for (int d = 8; d >= 1; d >>= 1)
                rs += __shfl_xor_sync(0xffffffffu, rs, d, 16);
            li[i] = li[i] * alpha + rs;
            mi[i] = mnew;
#pragma unroll
            for (int jo = 0; jo < 8; jo++) o[i][jo] *= alpha;
        }
        __syncthreads();

#pragma unroll 4
        for (int n4 = 0; n4 < 64; n4 += 4) {
            float4 af0 = *(const float4*)&sP[(ty * 4 + 0) * 68 + n4];
            float4 af1 = *(const float4*)&sP[(ty * 4 + 1) * 68 + n4];
            float4 af2 = *(const float4*)&sP[(ty * 4 + 2) * 68 + n4];
            float4 af3 = *(const float4*)&sP[(ty * 4 + 3) * 68 + n4];
#pragma unroll
            for (int nn = 0; nn < 4; nn++) {
                float4 v0 = *(const float4*)&sV[(n4 + nn) * 128 + tx * 4];
                float4 v1 = *(const float4*)&sV[(n4 + nn) * 128 + 64 + tx * 4];
                float p0 = f4c(af0, nn), p1 = f4c(af1, nn), p2 = f4c(af2, nn), p3 = f4c(af3, nn);
                o[0][0] += p0 * v0.x; o[0][1] += p0 * v0.y; o[0][2] += p0 * v0.z; o[0][3] += p0 * v0.w;
                o[0][4] += p0 * v1.x; o[0][5] += p0 * v1.y; o[0][6] += p0 * v1.z; o[0][7] += p0 * v1.w;
                o[1][0] += p1 * v0.x; o[1][1] += p1 * v0.y; o[1][2] += p1 * v0.z; o[1][3] += p1 * v0.w;
                o[1][4] += p1 * v1.x; o[1][5] += p1 * v1.y; o[1][6] += p1 * v1.z; o[1][7] += p1 * v1.w;
                o[2][0] += p2 * v0.x; o[2][1] += p2 * v0.y; o[2][2] += p2 * v0.z; o[2][3] += p2 * v0.w;
                o[2][4] += p2 * v1.x; o[2][5] += p2 * v1.y; o[2][6] += p2 * v1.z; o[2][7] += p2 * v1.w;
                o[3][0] += p3 * v0.x; o[3][1] += p3 * v0.y; o[3][2] += p3 * v0.z; o[3][3] += p3 * v0.w;
                o[3][4] += p3 * v1.x; o[3][5] += p3 * v1.y; o[3][6] += p3 * v1.z; o[3][7] += p3 * v1.w;
            }
        }
    }

#pragma unroll
    for (int i = 0; i < 4; i++) {
        float inv = 1.0f / li[i];
        int sp = qb * 64 + ty * 4 + i;
        float* dst = &ctx[(size_t)(sp * 2 + b) * CTXW + h * HDIM];
        float4 w0 = make_float4(o[i][0] * inv, o[i][1] * inv, o[i][2] * inv, o[i][3] * inv);
        float4 w1 = make_float4(o[i][4] * inv, o[i][5] * inv, o[i][6] * inv, o[i][7] * inv);
        *(float4*)&dst[tx * 4]      = w0;
        *(float4*)&dst[64 + tx * 4] = w1;
    }
}

// ---------------------------------------------------------------------------
// Launch
// ---------------------------------------------------------------------------
extern "C" void kernel_launch(void* const* d_in, const int* in_sizes, int n_in,
                              void* d_out, int out_size)
{
    const float* hidden  = (const float*)d_in[0];
    // d_in[1] = attention_mask (causal) — hardcoded, unused
    const float* rope    = (const float*)d_in[2];
    const float* W_qkv   = (const float*)d_in[3];
    const float* b_qkv   = (const float*)d_in[4];
    const float* W_dense = (const float*)d_in[5];
    float* out = (float*)d_out;

    float *mixed = nullptr, *ctx = nullptr;
    cudaGetSymbolAddress((void**)&mixed, g_mixed);
    cudaGetSymbolAddress((void**)&ctx, g_ctx);

    cudaFuncSetAttribute(attn_kernel, cudaFuncAttributeMaxDynamicSharedMemorySize,
                         ATTN_SMEM_BYTES);
    cudaFuncSetAttribute(gemm_tf32_3x, cudaFuncAttributeMaxDynamicSharedMemorySize,
                         GEMM3X_SMEM);

    // 1) QKV projection + bias (3xTF32 split: near-fp32 accuracy)
    gemm_tf32_3x<<<dim3(NQKV / 128, MROWS / 128), 256, GEMM3X_SMEM>>>(
        hidden, W_qkv, b_qkv, mixed, MROWS, NQKV, HID);

    // 2) Rotary on q + k
    {
        int total = MROWS * 34 * 32;
        rotary_kernel<<<(total + 255) / 256, 256>>>(mixed, rope);
    }

    // 3) Causal GQA attention -> ctx
    attn_kernel<<<dim3(SQL / 64, BATCH * NHEAD), 256, ATTN_SMEM_BYTES>>>(mixed, ctx);

    // 4) Dense projection (1xTF32)
    gemm_tf32_1x<<<dim3(CTXW / 128, MROWS / 128), 256>>>(
        ctx, W_dense, nullptr, out, MROWS, HID, CTXW);
}